// round 11
// baseline (speedup 1.0000x reference)
#include <cuda_runtime.h>

// Problem constants (fixed by the dataset)
#define BSZ   16384
#define KNUM  1000
#define DIMN  768

#define WARPS_PER_BLOCK 4
#define THREADS (WARPS_PER_BLOCK * 32)          // 128
#define BLOCKS (BSZ / WARPS_PER_BLOCK)          // 4096

#define V4_PER_LANE 6          // DIM/4/32
#define MASK_V4 (KNUM / 4)     // 250

__device__ __forceinline__ float4 ldcs4(const float4* p) {
    float4 v;
    asm volatile("ld.global.cs.v4.f32 {%0,%1,%2,%3}, [%4];"
                 : "=f"(v.x), "=f"(v.y), "=f"(v.z), "=f"(v.w) : "l"(p));
    return v;
}
__device__ __forceinline__ void stcs4(float4* p, float4 v) {
    asm volatile("st.global.cs.v4.f32 [%0], {%1,%2,%3,%4};"
                 :: "l"(p), "f"(v.x), "f"(v.y), "f"(v.z), "f"(v.w));
}

__global__ __launch_bounds__(THREADS, 6)
void css_kernel(const float* __restrict__ mask,   // [BS, K]
                const float* __restrict__ z,      // [BS, DIM] (unit rows)
                const float* __restrict__ S,      // [K, 2*DIM] (unit poles)
                const float* __restrict__ A,      // [K, 2]
                const float* __restrict__ LG,     // [K, 2]
                float* __restrict__ out)          // [BS, DIM]
{
    const int warp = (blockIdx.x * THREADS + threadIdx.x) >> 5;
    const int lane = threadIdx.x & 31;
    if (warp >= BSZ) return;

    // ---- 1. Mask scan: record the one-hot position seen by this lane.
    const float4* __restrict__ mrow =
        reinterpret_cast<const float4*>(mask + (size_t)warp * KNUM);
    int lidx = 0;
    #pragma unroll
    for (int it = 0; it < 8; it++) {
        int i = lane + 32 * it;
        if (i < MASK_V4) {
            float4 v = ldcs4(&mrow[i]);
            if (v.x != 0.0f) lidx = 4 * i + 0;
            if (v.y != 0.0f) lidx = 4 * i + 1;
            if (v.z != 0.0f) lidx = 4 * i + 2;
            if (v.w != 0.0f) lidx = 4 * i + 3;
        }
    }

    // ---- 2. z loads: independent of idx; issue now, retain in registers.
    const float4* __restrict__ zrow =
        reinterpret_cast<const float4*>(z + (size_t)warp * DIMN);
    float4 zr[V4_PER_LANE];
    #pragma unroll
    for (int i = 0; i < V4_PER_LANE; i++)
        zr[i] = ldcs4(&zrow[lane + 32 * i]);

    // ---- 3. Ballot-based idx broadcast (exact; ~40 cyc vs ~130 for shfl-reduce)
    unsigned found = __ballot_sync(0xffffffffu, lidx != 0);
    int idx = 0;
    if (found) {
        int src = __ffs(found) - 1;
        idx = __shfl_sync(0xffffffffu, lidx, src);
    }

    // ---- 4. Dipole scalars + S row gathers (registers, retained)
    const float2 Av = __ldg(reinterpret_cast<const float2*>(A)  + idx);
    const float2 Lv = __ldg(reinterpret_cast<const float2*>(LG) + idx);
    const float g0 = __expf(Lv.x), g1 = __expf(Lv.y);

    const float4* __restrict__ s0p =
        reinterpret_cast<const float4*>(S + (size_t)idx * (2 * DIMN));
    const float4* __restrict__ s1p = s0p + (DIMN / 4);

    float4 s0r[V4_PER_LANE], s1r[V4_PER_LANE];
    #pragma unroll
    for (int i = 0; i < V4_PER_LANE; i++) {
        const int p = lane + 32 * i;
        s0r[i] = __ldg(&s0p[p]);
        s1r[i] = __ldg(&s1p[p]);
    }

    // ---- 5. Three dot products (z, s0, s1 are unit vectors by construction)
    float c0 = 0.0f, c1 = 0.0f, s01 = 0.0f;
    #pragma unroll
    for (int i = 0; i < V4_PER_LANE; i++) {
        float4 zv = zr[i], s0 = s0r[i], s1 = s1r[i];
        c0  = fmaf(zv.x, s0.x, c0);   c0  = fmaf(zv.y, s0.y, c0);
        c0  = fmaf(zv.z, s0.z, c0);   c0  = fmaf(zv.w, s0.w, c0);
        c1  = fmaf(zv.x, s1.x, c1);   c1  = fmaf(zv.y, s1.y, c1);
        c1  = fmaf(zv.z, s1.z, c1);   c1  = fmaf(zv.w, s1.w, c1);
        s01 = fmaf(s0.x, s1.x, s01);  s01 = fmaf(s0.y, s1.y, s01);
        s01 = fmaf(s0.z, s1.z, s01);  s01 = fmaf(s0.w, s1.w, s01);
    }

    // ---- 6. Single combined reduction (3 independent shuffle chains)
    #pragma unroll
    for (int o = 16; o > 0; o >>= 1) {
        c0  += __shfl_xor_sync(0xffffffffu, c0,  o);
        c1  += __shfl_xor_sync(0xffffffffu, c1,  o);
        s01 += __shfl_xor_sync(0xffffffffu, s01, o);
    }

    // ---- 7. Scalar algebra (unit-norm form)
    const float sq0 = 2.0f - 2.0f * c0;
    const float sq1 = 2.0f - 2.0f * c1;
    const float w0  = -2.0f * Av.x * g0 * __expf(-g0 * sq0);
    const float w1  = -2.0f * Av.y * g1 * __expf(-g1 * sq1);
    const float beta = w0 * c0 + w1 * c1;   // proj = beta z - w0 s0 - w1 s1
    const float nrm2 = w0 * w0 + w1 * w1 + 2.0f * w0 * w1 * s01 - beta * beta;
    const float inv = rsqrtf(nrm2);
    const float bz = beta * inv;
    const float b0 = -w0 * inv;
    const float b1 = -w1 * inv;

    // ---- 8. Epilogue: pure register -> GMEM streamed stores (no reloads)
    float4* __restrict__ orow =
        reinterpret_cast<float4*>(out + (size_t)warp * DIMN);
    #pragma unroll
    for (int i = 0; i < V4_PER_LANE; i++) {
        float4 o4;
        o4.x = fmaf(bz, zr[i].x, fmaf(b0, s0r[i].x, b1 * s1r[i].x));
        o4.y = fmaf(bz, zr[i].y, fmaf(b0, s0r[i].y, b1 * s1r[i].y));
        o4.z = fmaf(bz, zr[i].z, fmaf(b0, s0r[i].z, b1 * s1r[i].z));
        o4.w = fmaf(bz, zr[i].w, fmaf(b0, s0r[i].w, b1 * s1r[i].w));
        stcs4(&orow[lane + 32 * i], o4);
    }
}

extern "C" void kernel_launch(void* const* d_in, const int* in_sizes, int n_in,
                              void* d_out, int out_size)
{
    const float* mask = (const float*)d_in[0];   // [BS, K]
    const float* z    = (const float*)d_in[1];   // [BS, DIM]
    const float* S    = (const float*)d_in[2];   // [K, 2*DIM]
    const float* A    = (const float*)d_in[3];   // [K, 2]
    const float* LG   = (const float*)d_in[4];   // [K, 2]
    float* out        = (float*)d_out;           // [BS, DIM]

    css_kernel<<<BLOCKS, THREADS>>>(mask, z, S, A, LG, out);
}

// round 12
// speedup vs baseline: 1.0802x; 1.0802x over previous
#include <cuda_runtime.h>

// Problem constants (fixed by the dataset)
#define BSZ   16384
#define KNUM  1000
#define DIMN  768

#define WARPS_PER_BLOCK 4
#define THREADS (WARPS_PER_BLOCK * 32)          // 128
#define BLOCKS (BSZ / WARPS_PER_BLOCK)          // 4096

#define V4_PER_LANE 6          // DIM/4/32
#define MASK_V4 (KNUM / 4)     // 250

__device__ __forceinline__ float4 ldcs4(const float4* p) {
    float4 v;
    asm volatile("ld.global.cs.v4.f32 {%0,%1,%2,%3}, [%4];"
                 : "=f"(v.x), "=f"(v.y), "=f"(v.z), "=f"(v.w) : "l"(p));
    return v;
}
__device__ __forceinline__ void stcs4(float4* p, float4 v) {
    asm volatile("st.global.cs.v4.f32 [%0], {%1,%2,%3,%4};"
                 :: "l"(p), "f"(v.x), "f"(v.y), "f"(v.z), "f"(v.w));
}

__global__ __launch_bounds__(THREADS, 5)
void css_kernel(const float* __restrict__ mask,   // [BS, K]
                const float* __restrict__ z,      // [BS, DIM] (unit rows)
                const float* __restrict__ S,      // [K, 2*DIM] (unit poles)
                const float* __restrict__ A,      // [K, 2]
                const float* __restrict__ LG,     // [K, 2]
                float* __restrict__ out)          // [BS, DIM]
{
    const int warp = (blockIdx.x * THREADS + threadIdx.x) >> 5;
    const int lane = threadIdx.x & 31;

    // ---- 1. Mask scan: record the one-hot position seen by this lane.
    const float4* __restrict__ mrow =
        reinterpret_cast<const float4*>(mask + (size_t)warp * KNUM);
    int lidx = 0;
    #pragma unroll
    for (int it = 0; it < 8; it++) {
        int i = lane + 32 * it;
        if (i < MASK_V4) {
            float4 v = ldcs4(&mrow[i]);
            if (v.x != 0.0f) lidx = 4 * i + 0;
            if (v.y != 0.0f) lidx = 4 * i + 1;
            if (v.z != 0.0f) lidx = 4 * i + 2;
            if (v.w != 0.0f) lidx = 4 * i + 3;
        }
    }

    // ---- 2. z loads: independent of idx; issue now, retain in registers.
    const float4* __restrict__ zrow =
        reinterpret_cast<const float4*>(z + (size_t)warp * DIMN);
    float4 zr[V4_PER_LANE];
    #pragma unroll
    for (int i = 0; i < V4_PER_LANE; i++)
        zr[i] = ldcs4(&zrow[lane + 32 * i]);

    // ---- 3. Ballot-based idx broadcast (branchless, exact).
    //         If no lane saw a nonzero (one-hot at position 0), all lidx
    //         are 0 and any source lane yields the correct idx = 0.
    unsigned found = __ballot_sync(0xffffffffu, lidx != 0);
    int src = max((int)__ffs(found) - 1, 0);
    int idx = __shfl_sync(0xffffffffu, lidx, src);

    // ---- 4. Dipole scalars + S row gathers (registers, retained)
    const float2 Av = __ldg(reinterpret_cast<const float2*>(A)  + idx);
    const float2 Lv = __ldg(reinterpret_cast<const float2*>(LG) + idx);
    const float g0 = __expf(Lv.x), g1 = __expf(Lv.y);

    const float4* __restrict__ s0p =
        reinterpret_cast<const float4*>(S + (size_t)idx * (2 * DIMN));
    const float4* __restrict__ s1p = s0p + (DIMN / 4);

    float4 s0r[V4_PER_LANE], s1r[V4_PER_LANE];
    #pragma unroll
    for (int i = 0; i < V4_PER_LANE; i++) {
        const int p = lane + 32 * i;
        s0r[i] = __ldg(&s0p[p]);
        s1r[i] = __ldg(&s1p[p]);
    }

    // ---- 5. Three dot products (z, s0, s1 are unit vectors by construction)
    float c0 = 0.0f, c1 = 0.0f, s01 = 0.0f;
    #pragma unroll
    for (int i = 0; i < V4_PER_LANE; i++) {
        float4 zv = zr[i], s0 = s0r[i], s1 = s1r[i];
        c0  = fmaf(zv.x, s0.x, c0);   c0  = fmaf(zv.y, s0.y, c0);
        c0  = fmaf(zv.z, s0.z, c0);   c0  = fmaf(zv.w, s0.w, c0);
        c1  = fmaf(zv.x, s1.x, c1);   c1  = fmaf(zv.y, s1.y, c1);
        c1  = fmaf(zv.z, s1.z, c1);   c1  = fmaf(zv.w, s1.w, c1);
        s01 = fmaf(s0.x, s1.x, s01);  s01 = fmaf(s0.y, s1.y, s01);
        s01 = fmaf(s0.z, s1.z, s01);  s01 = fmaf(s0.w, s1.w, s01);
    }

    // ---- 6. Single combined reduction (3 independent shuffle chains)
    #pragma unroll
    for (int o = 16; o > 0; o >>= 1) {
        c0  += __shfl_xor_sync(0xffffffffu, c0,  o);
        c1  += __shfl_xor_sync(0xffffffffu, c1,  o);
        s01 += __shfl_xor_sync(0xffffffffu, s01, o);
    }

    // ---- 7. Scalar algebra (unit-norm form)
    const float sq0 = 2.0f - 2.0f * c0;
    const float sq1 = 2.0f - 2.0f * c1;
    const float w0  = -2.0f * Av.x * g0 * __expf(-g0 * sq0);
    const float w1  = -2.0f * Av.y * g1 * __expf(-g1 * sq1);
    const float beta = w0 * c0 + w1 * c1;   // proj = beta z - w0 s0 - w1 s1
    const float nrm2 = w0 * w0 + w1 * w1 + 2.0f * w0 * w1 * s01 - beta * beta;
    const float inv = rsqrtf(nrm2);
    const float bz = beta * inv;
    const float b0 = -w0 * inv;
    const float b1 = -w1 * inv;

    // ---- 8. Epilogue: pure register -> GMEM streamed stores (no reloads)
    float4* __restrict__ orow =
        reinterpret_cast<float4*>(out + (size_t)warp * DIMN);
    #pragma unroll
    for (int i = 0; i < V4_PER_LANE; i++) {
        float4 o4;
        o4.x = fmaf(bz, zr[i].x, fmaf(b0, s0r[i].x, b1 * s1r[i].x));
        o4.y = fmaf(bz, zr[i].y, fmaf(b0, s0r[i].y, b1 * s1r[i].y));
        o4.z = fmaf(bz, zr[i].z, fmaf(b0, s0r[i].z, b1 * s1r[i].z));
        o4.w = fmaf(bz, zr[i].w, fmaf(b0, s0r[i].w, b1 * s1r[i].w));
        stcs4(&orow[lane + 32 * i], o4);
    }
}

extern "C" void kernel_launch(void* const* d_in, const int* in_sizes, int n_in,
                              void* d_out, int out_size)
{
    const float* mask = (const float*)d_in[0];   // [BS, K]
    const float* z    = (const float*)d_in[1];   // [BS, DIM]
    const float* S    = (const float*)d_in[2];   // [K, 2*DIM]
    const float* A    = (const float*)d_in[3];   // [K, 2]
    const float* LG   = (const float*)d_in[4];   // [K, 2]
    float* out        = (float*)d_out;           // [BS, DIM]

    css_kernel<<<BLOCKS, THREADS>>>(mask, z, S, A, LG, out);
}

// round 13
// speedup vs baseline: 1.1592x; 1.0731x over previous
#include <cuda_runtime.h>

// Problem constants (fixed by the dataset)
#define BSZ   16384
#define KNUM  1000
#define DIMN  768

#define WARPS_PER_BLOCK 4
#define THREADS (WARPS_PER_BLOCK * 32)          // 128
// Persistent grid: exactly one wave at 5 CTAs/SM on 148 SMs
#define BLOCKS 740
#define NWARPS (BLOCKS * WARPS_PER_BLOCK)       // 2960

#define V4_PER_LANE 6          // DIM/4/32
#define MASK_V4 (KNUM / 4)     // 250

__device__ __forceinline__ float4 ldcs4(const float4* p) {
    float4 v;
    asm volatile("ld.global.cs.v4.f32 {%0,%1,%2,%3}, [%4];"
                 : "=f"(v.x), "=f"(v.y), "=f"(v.z), "=f"(v.w) : "l"(p));
    return v;
}
__device__ __forceinline__ void stcs4(float4* p, float4 v) {
    asm volatile("st.global.cs.v4.f32 [%0], {%1,%2,%3,%4};"
                 :: "l"(p), "f"(v.x), "f"(v.y), "f"(v.z), "f"(v.w));
}

__global__ __launch_bounds__(THREADS, 5)
void css_kernel(const float* __restrict__ mask,   // [BS, K]
                const float* __restrict__ z,      // [BS, DIM] (unit rows)
                const float* __restrict__ S,      // [K, 2*DIM] (unit poles)
                const float* __restrict__ A,      // [K, 2]
                const float* __restrict__ LG,     // [K, 2]
                float* __restrict__ out)          // [BS, DIM]
{
    const int warp0 = (blockIdx.x * THREADS + threadIdx.x) >> 5;
    const int lane  = threadIdx.x & 31;

    // Persistent grid-stride loop: concurrent warps touch adjacent rows.
    for (int smp = warp0; smp < BSZ; smp += NWARPS) {

        // ---- 1. Mask scan: record the one-hot position seen by this lane.
        const float4* __restrict__ mrow =
            reinterpret_cast<const float4*>(mask + (size_t)smp * KNUM);
        int lidx = 0;
        #pragma unroll
        for (int it = 0; it < 8; it++) {
            int i = lane + 32 * it;
            if (i < MASK_V4) {
                float4 v = ldcs4(&mrow[i]);
                if (v.x != 0.0f) lidx = 4 * i + 0;
                if (v.y != 0.0f) lidx = 4 * i + 1;
                if (v.z != 0.0f) lidx = 4 * i + 2;
                if (v.w != 0.0f) lidx = 4 * i + 3;
            }
        }

        // ---- 2. z loads: independent of idx; issue now, retain in registers.
        const float4* __restrict__ zrow =
            reinterpret_cast<const float4*>(z + (size_t)smp * DIMN);
        float4 zr[V4_PER_LANE];
        #pragma unroll
        for (int i = 0; i < V4_PER_LANE; i++)
            zr[i] = ldcs4(&zrow[lane + 32 * i]);

        // ---- 3. Ballot-based idx broadcast (branchless, exact).
        unsigned found = __ballot_sync(0xffffffffu, lidx != 0);
        int src = max((int)__ffs(found) - 1, 0);
        int idx = __shfl_sync(0xffffffffu, lidx, src);

        // ---- 4. Dipole scalars + S row gathers (registers, retained)
        const float2 Av = __ldg(reinterpret_cast<const float2*>(A)  + idx);
        const float2 Lv = __ldg(reinterpret_cast<const float2*>(LG) + idx);
        const float g0 = __expf(Lv.x), g1 = __expf(Lv.y);

        const float4* __restrict__ s0p =
            reinterpret_cast<const float4*>(S + (size_t)idx * (2 * DIMN));
        const float4* __restrict__ s1p = s0p + (DIMN / 4);

        float4 s0r[V4_PER_LANE], s1r[V4_PER_LANE];
        #pragma unroll
        for (int i = 0; i < V4_PER_LANE; i++) {
            const int p = lane + 32 * i;
            s0r[i] = __ldg(&s0p[p]);
            s1r[i] = __ldg(&s1p[p]);
        }

        // ---- 5. Three dot products (z, s0, s1 unit vectors by construction)
        float c0 = 0.0f, c1 = 0.0f, s01 = 0.0f;
        #pragma unroll
        for (int i = 0; i < V4_PER_LANE; i++) {
            float4 zv = zr[i], s0 = s0r[i], s1 = s1r[i];
            c0  = fmaf(zv.x, s0.x, c0);   c0  = fmaf(zv.y, s0.y, c0);
            c0  = fmaf(zv.z, s0.z, c0);   c0  = fmaf(zv.w, s0.w, c0);
            c1  = fmaf(zv.x, s1.x, c1);   c1  = fmaf(zv.y, s1.y, c1);
            c1  = fmaf(zv.z, s1.z, c1);   c1  = fmaf(zv.w, s1.w, c1);
            s01 = fmaf(s0.x, s1.x, s01);  s01 = fmaf(s0.y, s1.y, s01);
            s01 = fmaf(s0.z, s1.z, s01);  s01 = fmaf(s0.w, s1.w, s01);
        }

        // ---- 6. Single combined reduction (3 independent shuffle chains)
        #pragma unroll
        for (int o = 16; o > 0; o >>= 1) {
            c0  += __shfl_xor_sync(0xffffffffu, c0,  o);
            c1  += __shfl_xor_sync(0xffffffffu, c1,  o);
            s01 += __shfl_xor_sync(0xffffffffu, s01, o);
        }

        // ---- 7. Scalar algebra (unit-norm form)
        const float sq0 = 2.0f - 2.0f * c0;
        const float sq1 = 2.0f - 2.0f * c1;
        const float w0  = -2.0f * Av.x * g0 * __expf(-g0 * sq0);
        const float w1  = -2.0f * Av.y * g1 * __expf(-g1 * sq1);
        const float beta = w0 * c0 + w1 * c1;  // proj = beta z - w0 s0 - w1 s1
        const float nrm2 = w0 * w0 + w1 * w1 + 2.0f * w0 * w1 * s01
                         - beta * beta;
        const float inv = rsqrtf(nrm2);
        const float bz = beta * inv;
        const float b0 = -w0 * inv;
        const float b1 = -w1 * inv;

        // ---- 8. Epilogue: pure register -> GMEM streamed stores
        float4* __restrict__ orow =
            reinterpret_cast<float4*>(out + (size_t)smp * DIMN);
        #pragma unroll
        for (int i = 0; i < V4_PER_LANE; i++) {
            float4 o4;
            o4.x = fmaf(bz, zr[i].x, fmaf(b0, s0r[i].x, b1 * s1r[i].x));
            o4.y = fmaf(bz, zr[i].y, fmaf(b0, s0r[i].y, b1 * s1r[i].y));
            o4.z = fmaf(bz, zr[i].z, fmaf(b0, s0r[i].z, b1 * s1r[i].z));
            o4.w = fmaf(bz, zr[i].w, fmaf(b0, s0r[i].w, b1 * s1r[i].w));
            stcs4(&orow[lane + 32 * i], o4);
        }
    }
}

extern "C" void kernel_launch(void* const* d_in, const int* in_sizes, int n_in,
                              void* d_out, int out_size)
{
    const float* mask = (const float*)d_in[0];   // [BS, K]
    const float* z    = (const float*)d_in[1];   // [BS, DIM]
    const float* S    = (const float*)d_in[2];   // [K, 2*DIM]
    const float* A    = (const float*)d_in[3];   // [K, 2]
    const float* LG   = (const float*)d_in[4];   // [K, 2]
    float* out        = (float*)d_out;           // [BS, DIM]

    css_kernel<<<BLOCKS, THREADS>>>(mask, z, S, A, LG, out);
}